// round 1
// baseline (speedup 1.0000x reference)
#include <cuda_runtime.h>
#include <cstdint>

#define NB 2
#define NT 2048
#define NC 1024
#define NH 16
#define DH 64

// fp32 scratch (device globals: no allocation in kernel_launch)
__device__ float g_q[NB * NH * NT * DH];
__device__ float g_k[NB * NH * NT * DH];
__device__ float g_v[NB * NH * NT * DH];
__device__ float g_y[NB * NT * NC];

__device__ __forceinline__ uint32_t f2t(float f) {
    uint32_t u;
    asm("cvt.rna.tf32.f32 %0, %1;" : "=r"(u) : "f"(f));
    return u;
}

__device__ __forceinline__ void mma8(float d[4], const uint32_t a[4],
                                     uint32_t b0, uint32_t b1) {
    asm volatile(
        "mma.sync.aligned.m16n8k8.row.col.f32.tf32.tf32.f32 "
        "{%0,%1,%2,%3}, {%4,%5,%6,%7}, {%8,%9}, {%0,%1,%2,%3};\n"
        : "+f"(d[0]), "+f"(d[1]), "+f"(d[2]), "+f"(d[3])
        : "r"(a[0]), "r"(a[1]), "r"(a[2]), "r"(a[3]), "r"(b0), "r"(b1));
}

// ---------------------------------------------------------------------------
// Generic tf32 GEMM: out = A[M,K] @ W[K,N] (+bias).
// MODE 0: QKV projection, scatter epilogue into g_k/g_q/g_v (q scaled 0.125).
// MODE 1: output projection, A taken from g_y, plain fp32 out + bias.
// Block: 256 threads (8 warps, 2x4), tile 128x128, BK=32.
// ---------------------------------------------------------------------------
template <int MODE>
__global__ __launch_bounds__(256) void gemm_k(const float* __restrict__ A,
                                              const float* __restrict__ W,
                                              const float* __restrict__ bias,
                                              float* __restrict__ out,
                                              int K, int N) {
    __shared__ float As[128][36];   // pad 32->36: conflict-free frag reads
    __shared__ float Bs[32][136];   // pad 128->136
    const float* Ap = (MODE == 1) ? g_y : A;

    int tid = threadIdx.x;
    int warp = tid >> 5, lane = tid & 31;
    int g = lane >> 2, t = lane & 3;
    int wm = warp >> 2, wn = warp & 3;       // 2 x 4 warp grid
    int m0 = blockIdx.y * 128, n0 = blockIdx.x * 128;

    float acc[4][4][4];
#pragma unroll
    for (int mi = 0; mi < 4; mi++)
#pragma unroll
        for (int ni = 0; ni < 4; ni++)
#pragma unroll
            for (int e = 0; e < 4; e++) acc[mi][ni][e] = 0.0f;

    for (int kt = 0; kt < K; kt += 32) {
#pragma unroll
        for (int p = 0; p < 4; p++) {
            int idx = tid + p * 256;
            int r = idx >> 3, c = (idx & 7) * 4;
            float4 v = *(const float4*)(Ap + (size_t)(m0 + r) * K + kt + c);
            As[r][c] = v.x; As[r][c + 1] = v.y;
            As[r][c + 2] = v.z; As[r][c + 3] = v.w;
        }
#pragma unroll
        for (int p = 0; p < 4; p++) {
            int idx = tid + p * 256;
            int r = idx >> 5, c = (idx & 31) * 4;
            float4 v = *(const float4*)(W + (size_t)(kt + r) * N + n0 + c);
            Bs[r][c] = v.x; Bs[r][c + 1] = v.y;
            Bs[r][c + 2] = v.z; Bs[r][c + 3] = v.w;
        }
        __syncthreads();

#pragma unroll
        for (int kk = 0; kk < 4; kk++) {
            int k0 = kk * 8;
            uint32_t af[4][4];
#pragma unroll
            for (int mi = 0; mi < 4; mi++) {
                int r = wm * 64 + mi * 16;
                af[mi][0] = f2t(As[r + g][k0 + t]);
                af[mi][1] = f2t(As[r + g + 8][k0 + t]);
                af[mi][2] = f2t(As[r + g][k0 + t + 4]);
                af[mi][3] = f2t(As[r + g + 8][k0 + t + 4]);
            }
            uint32_t bf[4][2];
#pragma unroll
            for (int ni = 0; ni < 4; ni++) {
                int c = wn * 32 + ni * 8 + g;
                bf[ni][0] = f2t(Bs[k0 + t][c]);
                bf[ni][1] = f2t(Bs[k0 + t + 4][c]);
            }
#pragma unroll
            for (int mi = 0; mi < 4; mi++)
#pragma unroll
                for (int ni = 0; ni < 4; ni++)
                    mma8(acc[mi][ni], af[mi], bf[ni][0], bf[ni][1]);
        }
        __syncthreads();
    }

    // Epilogue. C frag: c0=(g, 2t), c1=(g, 2t+1), c2=(g+8, 2t), c3=(g+8, 2t+1)
#pragma unroll
    for (int mi = 0; mi < 4; mi++)
#pragma unroll
        for (int ni = 0; ni < 4; ni++)
#pragma unroll
            for (int e = 0; e < 4; e++) {
                int m = m0 + wm * 64 + mi * 16 + g + ((e >= 2) ? 8 : 0);
                int n = n0 + wn * 32 + ni * 8 + t * 2 + (e & 1);
                float val = acc[mi][ni][e] + bias[n];
                if (MODE == 0) {
                    int b = m >> 11, tt = m & (NT - 1);
                    int head = n / 192;
                    int r = n - head * 192;
                    int kind = r >> 6, d = r & 63;   // split order: k, q, v
                    size_t idx = ((size_t)(b * NH + head) * NT + tt) * DH + d;
                    if (kind == 0)      g_k[idx] = val;
                    else if (kind == 1) g_q[idx] = val * 0.125f;  // fold scale
                    else                g_v[idx] = val;
                } else {
                    out[(size_t)m * NC + n] = val;
                }
            }
}

// ---------------------------------------------------------------------------
// Causal flash attention. Grid (T/64, B*H), block 128 (4 warps).
// Each warp owns 16 query rows; 64-key tiles staged in smem.
// tf32 mma for QK^T and PV; online softmax in C-fragments.
// ---------------------------------------------------------------------------
__global__ __launch_bounds__(128) void attn_k() {
    __shared__ float Ks[64][68];   // pad 68: QK frag reads conflict-free
    __shared__ float Vs[64][72];   // pad 72: PV frag reads conflict-free

    int tid = threadIdx.x, w = tid >> 5, lane = tid & 31;
    int g = lane >> 2, t = lane & 3;
    int bh = blockIdx.y;
    int qb = blockIdx.x;                       // 64-row query tile index
    size_t base = (size_t)bh * NT * DH;
    int r0 = qb * 64 + w * 16;                 // warp's first query row

    // Load Q fragments once (q already scaled by 1/sqrt(hd))
    uint32_t qf[8][4];
    const float* qp = g_q + base + (size_t)r0 * DH;
#pragma unroll
    for (int kk = 0; kk < 8; kk++) {
        qf[kk][0] = f2t(qp[g * DH + kk * 8 + t]);
        qf[kk][1] = f2t(qp[(g + 8) * DH + kk * 8 + t]);
        qf[kk][2] = f2t(qp[g * DH + kk * 8 + t + 4]);
        qf[kk][3] = f2t(qp[(g + 8) * DH + kk * 8 + t + 4]);
    }

    float o[8][4];
#pragma unroll
    for (int jd = 0; jd < 8; jd++)
#pragma unroll
        for (int e = 0; e < 4; e++) o[jd][e] = 0.0f;
    float mrow[2] = {-1e30f, -1e30f};
    float lrow[2] = {0.0f, 0.0f};

    const unsigned FULL = 0xffffffffu;
    int s1 = (lane & ~3) | (t >> 1);   // src lane for P col t
    int s2 = s1 + 2;                   // src lane for P col t+4

    for (int kt = 0; kt <= qb; kt++) {
        __syncthreads();
        const float* kp = g_k + base + (size_t)kt * 64 * DH;
        const float* vp = g_v + base + (size_t)kt * 64 * DH;
#pragma unroll
        for (int p = 0; p < 8; p++) {
            int idx = tid + p * 128;
            int r = idx >> 4, c = (idx & 15) * 4;
            float4 k4 = *(const float4*)(kp + r * DH + c);
            Ks[r][c] = k4.x; Ks[r][c + 1] = k4.y;
            Ks[r][c + 2] = k4.z; Ks[r][c + 3] = k4.w;
            float4 v4 = *(const float4*)(vp + r * DH + c);
            Vs[r][c] = v4.x; Vs[r][c + 1] = v4.y;
            Vs[r][c + 2] = v4.z; Vs[r][c + 3] = v4.w;
        }
        __syncthreads();

        // S = Q K^T over 8 key n-tiles, 8 k8-steps of d
        float s[8][4];
#pragma unroll
        for (int j = 0; j < 8; j++)
#pragma unroll
            for (int e = 0; e < 4; e++) s[j][e] = 0.0f;
#pragma unroll
        for (int kk = 0; kk < 8; kk++) {
#pragma unroll
            for (int j = 0; j < 8; j++) {
                uint32_t b0 = f2t(Ks[j * 8 + g][kk * 8 + t]);
                uint32_t b1 = f2t(Ks[j * 8 + g][kk * 8 + t + 4]);
                mma8(s[j], qf[kk], b0, b1);
            }
        }

        // Causal mask: only the diagonal tile is partial
        if (kt == qb) {
#pragma unroll
            for (int j = 0; j < 8; j++) {
                int key = kt * 64 + j * 8 + t * 2;
                if (key > r0 + g)         s[j][0] = -1e30f;
                if (key + 1 > r0 + g)     s[j][1] = -1e30f;
                if (key > r0 + g + 8)     s[j][2] = -1e30f;
                if (key + 1 > r0 + g + 8) s[j][3] = -1e30f;
            }
        }

        // Online softmax per row-half (rows g and g+8)
#pragma unroll
        for (int h2 = 0; h2 < 2; h2++) {
            float tm = -1e30f;
#pragma unroll
            for (int j = 0; j < 8; j++)
                tm = fmaxf(tm, fmaxf(s[j][h2 * 2], s[j][h2 * 2 + 1]));
            tm = fmaxf(tm, __shfl_xor_sync(FULL, tm, 1));
            tm = fmaxf(tm, __shfl_xor_sync(FULL, tm, 2));
            float nm = fmaxf(mrow[h2], tm);
            float corr = __expf(mrow[h2] - nm);
            mrow[h2] = nm;
            float sum = 0.0f;
#pragma unroll
            for (int j = 0; j < 8; j++) {
                float p0 = __expf(s[j][h2 * 2] - nm);
                float p1 = __expf(s[j][h2 * 2 + 1] - nm);
                s[j][h2 * 2] = p0; s[j][h2 * 2 + 1] = p1;
                sum += p0 + p1;
            }
            sum += __shfl_xor_sync(FULL, sum, 1);
            sum += __shfl_xor_sync(FULL, sum, 2);
            lrow[h2] = lrow[h2] * corr + sum;
#pragma unroll
            for (int jd = 0; jd < 8; jd++) {
                o[jd][h2 * 2] *= corr;
                o[jd][h2 * 2 + 1] *= corr;
            }
        }

        // O += P V : re-fragment P (C-layout cols 2t,2t+1 -> A-layout cols t,t+4)
        bool odd = (t & 1);
#pragma unroll
        for (int kk = 0; kk < 8; kk++) {
            float c0 = s[kk][0], c1 = s[kk][1], c2 = s[kk][2], c3 = s[kk][3];
            float v0a = __shfl_sync(FULL, c0, s1), v0b = __shfl_sync(FULL, c1, s1);
            float v1a = __shfl_sync(FULL, c2, s1), v1b = __shfl_sync(FULL, c3, s1);
            float v2a = __shfl_sync(FULL, c0, s2), v2b = __shfl_sync(FULL, c1, s2);
            float v3a = __shfl_sync(FULL, c2, s2), v3b = __shfl_sync(FULL, c3, s2);
            uint32_t pa[4];
            pa[0] = f2t(odd ? v0b : v0a);
            pa[1] = f2t(odd ? v1b : v1a);
            pa[2] = f2t(odd ? v2b : v2a);
            pa[3] = f2t(odd ? v3b : v3a);
#pragma unroll
            for (int jd = 0; jd < 8; jd++) {
                uint32_t b0 = f2t(Vs[kk * 8 + t][jd * 8 + g]);
                uint32_t b1 = f2t(Vs[kk * 8 + t + 4][jd * 8 + g]);
                mma8(o[jd], pa, b0, b1);
            }
        }
    }

    // Normalize and write y[b, t, h*64+d]
    int b = bh >> 4, head = bh & 15;
    float inv0 = 1.0f / lrow[0], inv1 = 1.0f / lrow[1];
#pragma unroll
    for (int jd = 0; jd < 8; jd++) {
        int d = head * 64 + jd * 8 + t * 2;
        float* y0 = g_y + (size_t)(b * NT + r0 + g) * NC + d;
        float* y1 = g_y + (size_t)(b * NT + r0 + g + 8) * NC + d;
        y0[0] = o[jd][0] * inv0; y0[1] = o[jd][1] * inv0;
        y1[0] = o[jd][2] * inv1; y1[1] = o[jd][3] * inv1;
    }
}

// ---------------------------------------------------------------------------
extern "C" void kernel_launch(void* const* d_in, const int* in_sizes, int n_in,
                              void* d_out, int out_size) {
    (void)in_sizes; (void)n_in; (void)out_size;
    const float* x      = (const float*)d_in[0];
    // d_in[1] = att_mask: causal tril by construction; masking is hardcoded.
    const float* w_kqv  = (const float*)d_in[2];
    const float* b_kqv  = (const float*)d_in[3];
    const float* w_proj = (const float*)d_in[4];
    const float* b_proj = (const float*)d_in[5];
    float* out = (float*)d_out;

    // 1) kqv = x @ w_kqv + b, scattered to K/Q/V scratch (q pre-scaled)
    gemm_k<0><<<dim3(24, 32), 256>>>(x, w_kqv, b_kqv, nullptr, NC, 3 * NC);
    // 2) causal flash attention -> g_y
    attn_k<<<dim3(NT / 64, NB * NH), 128>>>();
    // 3) out = y @ w_proj + b
    gemm_k<1><<<dim3(8, 32), 256>>>(nullptr, w_proj, b_proj, out, NC, NC);
}